// round 1
// baseline (speedup 1.0000x reference)
#include <cuda_runtime.h>
#include <math.h>

// ---------------- model constants ----------------
#define BB     16
#define EDIM   768
#define NHEADS 12
#define HD     64
#define FFDIM  3072
#define NLAYER 8
#define SEQ    64
#define ROWSM  1024     // BB*SEQ
#define PDIM   4096

// ---------------- scratch (device globals; no allocations allowed) ----------
__device__ float g_pool1[16 * 255 * 255 * 16];
__device__ float g_pool2[16 * 126 * 126 * 16];
__device__ float g_patches[ROWSM * PDIM];
__device__ float g_t [ROWSM * EDIM];
__device__ float g_q [ROWSM * EDIM];
__device__ float g_k [ROWSM * EDIM];
__device__ float g_v [ROWSM * EDIM];
__device__ float g_att[ROWSM * EDIM];
__device__ float g_a2[ROWSM * EDIM];
__device__ float g_o1[ROWSM * EDIM];
__device__ float g_f1[ROWSM * FFDIM];
__device__ float g_f2[ROWSM * EDIM];

// ---------------- conv1 (3x3x3->16) + relu + maxpool2x2, fused -------------
// one thread per (b, ph, pw), computes all 16 output channels
__global__ void conv1_pool_kernel(const float* __restrict__ x,
                                  const float* __restrict__ w,
                                  const float* __restrict__ bias,
                                  float* __restrict__ out) {
    __shared__ float ws[432];
    __shared__ float bs[16];
    int tid = threadIdx.x;
    for (int i = tid; i < 432; i += 256) ws[i] = w[i];
    if (tid < 16) bs[tid] = bias[tid];
    __syncthreads();

    int idx = blockIdx.x * 256 + tid;
    if (idx >= 16 * 255 * 255) return;
    int pw = idx % 255;
    int t  = idx / 255;
    int ph = t % 255;
    int b  = t / 255;

    float mx[16];
#pragma unroll
    for (int c = 0; c < 16; c++) mx[c] = 0.0f;  // relu outputs are >= 0

    for (int dy = 0; dy < 2; dy++) {
        for (int dx = 0; dx < 2; dx++) {
            int h0 = 2 * ph + dy;
            int w0 = 2 * pw + dx;
            float acc[16];
#pragma unroll
            for (int c = 0; c < 16; c++) acc[c] = bs[c];
            for (int kh = 0; kh < 3; kh++) {
                for (int kw = 0; kw < 3; kw++) {
                    const float* xp = x + (((long)(b * 512 + h0 + kh) * 512) + (w0 + kw)) * 3;
                    float x0 = xp[0], x1 = xp[1], x2 = xp[2];
                    const float* wp = ws + ((kh * 3 + kw) * 3) * 16;
#pragma unroll
                    for (int c = 0; c < 16; c++)
                        acc[c] += x0 * wp[c] + x1 * wp[16 + c] + x2 * wp[32 + c];
                }
            }
#pragma unroll
            for (int c = 0; c < 16; c++) mx[c] = fmaxf(mx[c], fmaxf(acc[c], 0.0f));
        }
    }
    float* op = out + (long)idx * 16;
#pragma unroll
    for (int c = 0; c < 16; c++) op[c] = mx[c];
}

// ---------------- conv2 (3x3x16->16) + relu + maxpool2x2, fused ------------
__global__ void conv2_pool_kernel(const float* __restrict__ in,
                                  const float* __restrict__ w,
                                  const float* __restrict__ bias,
                                  float* __restrict__ out) {
    __shared__ float ws[2304];
    __shared__ float bs[16];
    int tid = threadIdx.x;
    for (int i = tid; i < 2304; i += 256) ws[i] = w[i];
    if (tid < 16) bs[tid] = bias[tid];
    __syncthreads();

    int idx = blockIdx.x * 256 + tid;
    if (idx >= 16 * 126 * 126) return;
    int pw = idx % 126;
    int t  = idx / 126;
    int ph = t % 126;
    int b  = t / 126;

    float mx[16];
#pragma unroll
    for (int c = 0; c < 16; c++) mx[c] = 0.0f;

    for (int dy = 0; dy < 2; dy++) {
        for (int dx = 0; dx < 2; dx++) {
            int h0 = 2 * ph + dy;
            int w0 = 2 * pw + dx;
            float acc[16];
#pragma unroll
            for (int c = 0; c < 16; c++) acc[c] = bs[c];
            for (int kh = 0; kh < 3; kh++) {
                for (int kw = 0; kw < 3; kw++) {
                    const float* xp = in + ((long)(b * 255 + h0 + kh) * 255 + (w0 + kw)) * 16;
                    float xv[16];
#pragma unroll
                    for (int ci = 0; ci < 16; ci++) xv[ci] = xp[ci];
                    const float* wp = ws + ((kh * 3 + kw) * 16) * 16;
#pragma unroll
                    for (int ci = 0; ci < 16; ci++) {
#pragma unroll
                        for (int c = 0; c < 16; c++)
                            acc[c] += xv[ci] * wp[ci * 16 + c];
                    }
                }
            }
#pragma unroll
            for (int c = 0; c < 16; c++) mx[c] = fmaxf(mx[c], fmaxf(acc[c], 0.0f));
        }
    }
    float* op = out + (long)idx * 16;
#pragma unroll
    for (int c = 0; c < 16; c++) op[c] = mx[c];
}

// ---------------- patch gather: pad 126->128, extract 16x16 patches --------
__global__ void patch_kernel(const float* __restrict__ pool2,
                             float* __restrict__ patches) {
    long idx = (long)blockIdx.x * 256 + threadIdx.x;
    if (idx >= (long)ROWSM * PDIM) return;
    int d   = (int)(idx & (PDIM - 1));
    int row = (int)(idx >> 12);          // 0..1023
    int b   = row >> 6;
    int p   = row & 63;
    int pr  = p >> 3, pc = p & 7;
    int r   = d >> 8;
    int c   = (d >> 4) & 15;
    int ch  = d & 15;
    int H = pr * 16 + r;                 // 0..127 in padded space
    int W = pc * 16 + c;
    float v = 0.0f;
    if (H >= 1 && H <= 126 && W >= 1 && W <= 126)
        v = pool2[((long)(b * 126 + (H - 1)) * 126 + (W - 1)) * 16 + ch];
    patches[idx] = v;
}

// ---------------- generic SGEMM: C = A(MxK) * B(KxN) + bias, optional relu -
// 64x64 block tile, BK=16, 256 threads, 4x4 per thread. M,N%64==0, K%16==0.
__global__ void gemm_kernel(const float* __restrict__ A,
                            const float* __restrict__ B,
                            const float* __restrict__ bias,
                            float* __restrict__ C,
                            int M, int N, int K, int relu) {
    __shared__ float As[16][68];
    __shared__ float Bs[16][64];

    int bm = blockIdx.y * 64;
    int bn = blockIdx.x * 64;
    int tx = threadIdx.x, ty = threadIdx.y;
    int tid = ty * 16 + tx;

    float acc[4][4];
#pragma unroll
    for (int i = 0; i < 4; i++)
#pragma unroll
        for (int j = 0; j < 4; j++) acc[i][j] = 0.0f;

    for (int k0 = 0; k0 < K; k0 += 16) {
#pragma unroll
        for (int i = 0; i < 4; i++) {
            int t = tid + i * 256;
            int r = t >> 4, cc = t & 15;
            As[cc][r] = A[(long)(bm + r) * K + k0 + cc];
        }
#pragma unroll
        for (int i = 0; i < 4; i++) {
            int t = tid + i * 256;
            int r = t >> 6, cc = t & 63;
            Bs[r][cc] = B[(long)(k0 + r) * N + bn + cc];
        }
        __syncthreads();
#pragma unroll
        for (int kk = 0; kk < 16; kk++) {
            float4 av = *(const float4*)&As[kk][ty * 4];
            float4 bv = *(const float4*)&Bs[kk][tx * 4];
            acc[0][0] += av.x * bv.x; acc[0][1] += av.x * bv.y;
            acc[0][2] += av.x * bv.z; acc[0][3] += av.x * bv.w;
            acc[1][0] += av.y * bv.x; acc[1][1] += av.y * bv.y;
            acc[1][2] += av.y * bv.z; acc[1][3] += av.y * bv.w;
            acc[2][0] += av.z * bv.x; acc[2][1] += av.z * bv.y;
            acc[2][2] += av.z * bv.z; acc[2][3] += av.z * bv.w;
            acc[3][0] += av.w * bv.x; acc[3][1] += av.w * bv.y;
            acc[3][2] += av.w * bv.z; acc[3][3] += av.w * bv.w;
        }
        __syncthreads();
    }

    int col0 = bn + tx * 4;
    float4 bi = *(const float4*)&bias[col0];
#pragma unroll
    for (int i = 0; i < 4; i++) {
        int row = bm + ty * 4 + i;
        float4 v;
        v.x = acc[i][0] + bi.x; v.y = acc[i][1] + bi.y;
        v.z = acc[i][2] + bi.z; v.w = acc[i][3] + bi.w;
        if (relu) {
            v.x = fmaxf(v.x, 0.f); v.y = fmaxf(v.y, 0.f);
            v.z = fmaxf(v.z, 0.f); v.w = fmaxf(v.w, 0.f);
        }
        *(float4*)&C[(long)row * N + col0] = v;
    }
}

// ---------------- attention: one block per (b, head) ------------------------
// Writes output in FLAT (h, s, d) order per batch to replicate the reference's
// reshape-without-transpose:  out[b, h*4096 + s*64 + d]
__global__ void attn_kernel(const float* __restrict__ Q,
                            const float* __restrict__ K,
                            const float* __restrict__ V,
                            float* __restrict__ O) {
    extern __shared__ float sm[];
    float* qs = sm;                 // 64*65
    float* ks = qs + 64 * 65;
    float* vs = ks + 64 * 65;
    float* ss = vs + 64 * 65;

    int h = blockIdx.x;
    int b = blockIdx.y;
    int tid = threadIdx.x;

    for (int e = tid; e < 4096; e += 256) {
        int s = e >> 6, d = e & 63;
        long base = ((long)(b * 64 + s) * EDIM) + h * 64 + d;
        qs[s * 65 + d] = Q[base];
        ks[s * 65 + d] = K[base];
        vs[s * 65 + d] = V[base];
    }
    __syncthreads();

    // S = Q K^T * 0.125
    for (int e = tid; e < 4096; e += 256) {
        int row = e >> 6, col = e & 63;
        float sum = 0.0f;
#pragma unroll 16
        for (int dd = 0; dd < 64; dd++)
            sum += qs[row * 65 + dd] * ks[col * 65 + dd];
        ss[row * 65 + col] = sum * 0.125f;
    }
    __syncthreads();

    // softmax rows (one thread per row)
    if (tid < 64) {
        float* r = ss + tid * 65;
        float m = r[0];
#pragma unroll 16
        for (int c = 1; c < 64; c++) m = fmaxf(m, r[c]);
        float sum = 0.0f;
#pragma unroll 16
        for (int c = 0; c < 64; c++) { float e = expf(r[c] - m); r[c] = e; sum += e; }
        float inv = 1.0f / sum;
#pragma unroll 16
        for (int c = 0; c < 64; c++) r[c] *= inv;
    }
    __syncthreads();

    // A = S V, write flat (h,s,d)
    for (int e = tid; e < 4096; e += 256) {
        int row = e >> 6, d = e & 63;
        float sum = 0.0f;
#pragma unroll 16
        for (int col = 0; col < 64; col++)
            sum += ss[row * 65 + col] * vs[col * 65 + d];
        O[(long)b * (NHEADS * SEQ * HD) + h * 4096 + row * 64 + d] = sum;
    }
}

// ---------------- add + layernorm (row = 768) -------------------------------
__global__ void add_ln_kernel(const float* __restrict__ x,
                              const float* __restrict__ y,
                              const float* __restrict__ g,
                              const float* __restrict__ be,
                              float* __restrict__ out) {
    __shared__ float buf[EDIM];
    __shared__ float red[256];
    int row = blockIdx.x;
    int tid = threadIdx.x;
    long base = (long)row * EDIM;

    float partial = 0.0f;
    for (int e = tid; e < EDIM; e += 256) {
        float v = x[base + e] + y[base + e];
        buf[e] = v;
        partial += v;
    }
    red[tid] = partial;
    __syncthreads();
    for (int s = 128; s > 0; s >>= 1) {
        if (tid < s) red[tid] += red[tid + s];
        __syncthreads();
    }
    float mean = red[0] * (1.0f / EDIM);
    __syncthreads();

    float p2 = 0.0f;
    for (int e = tid; e < EDIM; e += 256) {
        float d = buf[e] - mean;
        p2 += d * d;
    }
    red[tid] = p2;
    __syncthreads();
    for (int s = 128; s > 0; s >>= 1) {
        if (tid < s) red[tid] += red[tid + s];
        __syncthreads();
    }
    float var = red[0] * (1.0f / EDIM);
    float rstd = rsqrtf(var + 1e-6f);

    for (int e = tid; e < EDIM; e += 256)
        out[base + e] = (buf[e] - mean) * rstd * g[e] + be[e];
}

// ---------------- mean-pool + head + sigmoid --------------------------------
__global__ void head_kernel(const float* __restrict__ t,
                            const float* __restrict__ hw,
                            const float* __restrict__ hb,
                            float* __restrict__ out) {
    __shared__ float red[256];
    int b = blockIdx.x;
    int tid = threadIdx.x;
    float partial = 0.0f;
    for (int e = tid; e < EDIM; e += 256) {
        float se = 0.0f;
        for (int s = 0; s < SEQ; s++)
            se += t[((long)(b * SEQ + s)) * EDIM + e];
        partial += (se * (1.0f / SEQ)) * hw[e];
    }
    red[tid] = partial;
    __syncthreads();
    for (int s = 128; s > 0; s >>= 1) {
        if (tid < s) red[tid] += red[tid + s];
        __syncthreads();
    }
    if (tid == 0) {
        float z = red[0] + hb[0];
        out[b] = 1.0f / (1.0f + expf(-z));
    }
}

// ---------------- host launch ------------------------------------------------
static inline void launch_gemm(const float* A, const float* B, const float* bias,
                               float* C, int M, int N, int K, int relu) {
    dim3 grid(N / 64, M / 64);
    dim3 block(16, 16);
    gemm_kernel<<<grid, block>>>(A, B, bias, C, M, N, K, relu);
}

extern "C" void kernel_launch(void* const* d_in, const int* in_sizes, int n_in,
                              void* d_out, int out_size) {
    const float* x       = (const float*)d_in[0];
    const float* conv1_w = (const float*)d_in[1];
    const float* conv1_b = (const float*)d_in[2];
    const float* conv2_w = (const float*)d_in[3];
    const float* conv2_b = (const float*)d_in[4];
    const float* proj_w  = (const float*)d_in[5];
    const float* proj_b  = (const float*)d_in[6];
    const float* Wq = (const float*)d_in[7];
    const float* bq = (const float*)d_in[8];
    const float* Wk = (const float*)d_in[9];
    const float* bk = (const float*)d_in[10];
    const float* Wv = (const float*)d_in[11];
    const float* bv = (const float*)d_in[12];
    const float* Wo = (const float*)d_in[13];
    const float* bo = (const float*)d_in[14];
    const float* W1 = (const float*)d_in[15];
    const float* b1 = (const float*)d_in[16];
    const float* W2 = (const float*)d_in[17];
    const float* b2 = (const float*)d_in[18];
    const float* ln1_g = (const float*)d_in[19];
    const float* ln1_b = (const float*)d_in[20];
    const float* ln2_g = (const float*)d_in[21];
    const float* ln2_b = (const float*)d_in[22];
    const float* head_w = (const float*)d_in[23];
    const float* head_b = (const float*)d_in[24];
    float* out = (float*)d_out;

    float *pool1, *pool2, *patches, *t, *q, *k, *v, *att, *a2, *o1, *f1, *f2;
    cudaGetSymbolAddress((void**)&pool1, g_pool1);
    cudaGetSymbolAddress((void**)&pool2, g_pool2);
    cudaGetSymbolAddress((void**)&patches, g_patches);
    cudaGetSymbolAddress((void**)&t,  g_t);
    cudaGetSymbolAddress((void**)&q,  g_q);
    cudaGetSymbolAddress((void**)&k,  g_k);
    cudaGetSymbolAddress((void**)&v,  g_v);
    cudaGetSymbolAddress((void**)&att, g_att);
    cudaGetSymbolAddress((void**)&a2, g_a2);
    cudaGetSymbolAddress((void**)&o1, g_o1);
    cudaGetSymbolAddress((void**)&f1, g_f1);
    cudaGetSymbolAddress((void**)&f2, g_f2);

    // attention kernel needs 4*64*65*4 = 66560 B dynamic smem
    const int attn_smem = 4 * 64 * 65 * sizeof(float);
    cudaFuncSetAttribute(attn_kernel, cudaFuncAttributeMaxDynamicSharedMemorySize, attn_smem);

    // conv stack
    {
        int n1 = 16 * 255 * 255;
        conv1_pool_kernel<<<(n1 + 255) / 256, 256>>>(x, conv1_w, conv1_b, pool1);
        int n2 = 16 * 126 * 126;
        conv2_pool_kernel<<<(n2 + 255) / 256, 256>>>(pool1, conv2_w, conv2_b, pool2);
        long np = (long)ROWSM * PDIM;
        patch_kernel<<<(int)((np + 255) / 256), 256>>>(pool2, patches);
    }

    // patch projection: t = patches @ proj_w + proj_b
    launch_gemm(patches, proj_w, proj_b, t, ROWSM, EDIM, PDIM, 0);

    for (int i = 0; i < NLAYER; i++) {
        const float* wq = Wq + (long)i * EDIM * EDIM;
        const float* wk = Wk + (long)i * EDIM * EDIM;
        const float* wv = Wv + (long)i * EDIM * EDIM;
        const float* wo = Wo + (long)i * EDIM * EDIM;
        const float* w1 = W1 + (long)i * EDIM * FFDIM;
        const float* w2 = W2 + (long)i * FFDIM * EDIM;

        launch_gemm(t, wq, bq + i * EDIM, q, ROWSM, EDIM, EDIM, 0);
        launch_gemm(t, wk, bk + i * EDIM, k, ROWSM, EDIM, EDIM, 0);
        launch_gemm(t, wv, bv + i * EDIM, v, ROWSM, EDIM, EDIM, 0);

        attn_kernel<<<dim3(NHEADS, BB), 256, attn_smem>>>(q, k, v, att);

        launch_gemm(att, wo, bo + i * EDIM, a2, ROWSM, EDIM, EDIM, 0);
        add_ln_kernel<<<ROWSM, 256>>>(t, a2, ln1_g + i * EDIM, ln1_b + i * EDIM, o1);
        launch_gemm(o1, w1, b1 + i * FFDIM, f1, ROWSM, FFDIM, EDIM, 1);
        launch_gemm(f1, w2, b2 + i * EDIM, f2, ROWSM, EDIM, FFDIM, 0);
        add_ln_kernel<<<ROWSM, 256>>>(o1, f2, ln2_g + i * EDIM, ln2_b + i * EDIM, t);
    }

    head_kernel<<<BB, 256>>>(t, head_w, head_b, out);
}

// round 2
// speedup vs baseline: 1.8391x; 1.8391x over previous
#include <cuda_runtime.h>
#include <math.h>
#include <stdint.h>

// ---------------- model constants ----------------
#define BB     16
#define EDIM   768
#define NHEADS 12
#define HD     64
#define FFDIM  3072
#define NLAYER 8
#define SEQ    64
#define ROWSM  1024     // BB*SEQ
#define PDIM   4096

// ---------------- scratch (device globals; no allocations allowed) ----------
__device__ float g_pool1[16 * 255 * 255 * 16];
__device__ float g_pool2[16 * 126 * 126 * 16];
__device__ float g_patches[ROWSM * PDIM];
__device__ float g_t [ROWSM * EDIM];
__device__ float g_q [ROWSM * EDIM];
__device__ float g_k [ROWSM * EDIM];
__device__ float g_v [ROWSM * EDIM];
__device__ float g_att[ROWSM * EDIM];
__device__ float g_a2[ROWSM * EDIM];
__device__ float g_o1[ROWSM * EDIM];
__device__ float g_f1[ROWSM * FFDIM];
__device__ float g_f2[ROWSM * EDIM];

// ---------------- conv1 (3x3x3->16) + relu + maxpool2x2, fused -------------
__global__ void conv1_pool_kernel(const float* __restrict__ x,
                                  const float* __restrict__ w,
                                  const float* __restrict__ bias,
                                  float* __restrict__ out) {
    __shared__ float ws[432];
    __shared__ float bs[16];
    int tid = threadIdx.x;
    for (int i = tid; i < 432; i += 256) ws[i] = w[i];
    if (tid < 16) bs[tid] = bias[tid];
    __syncthreads();

    int idx = blockIdx.x * 256 + tid;
    if (idx >= 16 * 255 * 255) return;
    int pw = idx % 255;
    int t  = idx / 255;
    int ph = t % 255;
    int b  = t / 255;

    float mx[16];
#pragma unroll
    for (int c = 0; c < 16; c++) mx[c] = 0.0f;

    for (int dy = 0; dy < 2; dy++) {
        for (int dx = 0; dx < 2; dx++) {
            int h0 = 2 * ph + dy;
            int w0 = 2 * pw + dx;
            float acc[16];
#pragma unroll
            for (int c = 0; c < 16; c++) acc[c] = bs[c];
            for (int kh = 0; kh < 3; kh++) {
                for (int kw = 0; kw < 3; kw++) {
                    const float* xp = x + (((long)(b * 512 + h0 + kh) * 512) + (w0 + kw)) * 3;
                    float x0 = xp[0], x1 = xp[1], x2 = xp[2];
                    const float* wp = ws + ((kh * 3 + kw) * 3) * 16;
#pragma unroll
                    for (int c = 0; c < 16; c++)
                        acc[c] += x0 * wp[c] + x1 * wp[16 + c] + x2 * wp[32 + c];
                }
            }
#pragma unroll
            for (int c = 0; c < 16; c++) mx[c] = fmaxf(mx[c], fmaxf(acc[c], 0.0f));
        }
    }
    float* op = out + (long)idx * 16;
#pragma unroll
    for (int c = 0; c < 16; c++) op[c] = mx[c];
}

// ---------------- conv2 (3x3x16->16) + relu + maxpool2x2, fused ------------
__global__ void conv2_pool_kernel(const float* __restrict__ in,
                                  const float* __restrict__ w,
                                  const float* __restrict__ bias,
                                  float* __restrict__ out) {
    __shared__ float ws[2304];
    __shared__ float bs[16];
    int tid = threadIdx.x;
    for (int i = tid; i < 2304; i += 256) ws[i] = w[i];
    if (tid < 16) bs[tid] = bias[tid];
    __syncthreads();

    int idx = blockIdx.x * 256 + tid;
    if (idx >= 16 * 126 * 126) return;
    int pw = idx % 126;
    int t  = idx / 126;
    int ph = t % 126;
    int b  = t / 126;

    float mx[16];
#pragma unroll
    for (int c = 0; c < 16; c++) mx[c] = 0.0f;

    for (int dy = 0; dy < 2; dy++) {
        for (int dx = 0; dx < 2; dx++) {
            int h0 = 2 * ph + dy;
            int w0 = 2 * pw + dx;
            float acc[16];
#pragma unroll
            for (int c = 0; c < 16; c++) acc[c] = bs[c];
            for (int kh = 0; kh < 3; kh++) {
                for (int kw = 0; kw < 3; kw++) {
                    const float* xp = in + ((long)(b * 255 + h0 + kh) * 255 + (w0 + kw)) * 16;
                    float xv[16];
#pragma unroll
                    for (int ci = 0; ci < 16; ci++) xv[ci] = xp[ci];
                    const float* wp = ws + ((kh * 3 + kw) * 16) * 16;
#pragma unroll
                    for (int ci = 0; ci < 16; ci++) {
#pragma unroll
                        for (int c = 0; c < 16; c++)
                            acc[c] += xv[ci] * wp[ci * 16 + c];
                    }
                }
            }
#pragma unroll
            for (int c = 0; c < 16; c++) mx[c] = fmaxf(mx[c], fmaxf(acc[c], 0.0f));
        }
    }
    float* op = out + (long)idx * 16;
#pragma unroll
    for (int c = 0; c < 16; c++) op[c] = mx[c];
}

// ---------------- patch gather -----------------------------------------------
__global__ void patch_kernel(const float* __restrict__ pool2,
                             float* __restrict__ patches) {
    long idx = (long)blockIdx.x * 256 + threadIdx.x;
    if (idx >= (long)ROWSM * PDIM) return;
    int d   = (int)(idx & (PDIM - 1));
    int row = (int)(idx >> 12);
    int b   = row >> 6;
    int p   = row & 63;
    int pr  = p >> 3, pc = p & 7;
    int r   = d >> 8;
    int c   = (d >> 4) & 15;
    int ch  = d & 15;
    int H = pr * 16 + r;
    int W = pc * 16 + c;
    float v = 0.0f;
    if (H >= 1 && H <= 126 && W >= 1 && W <= 126)
        v = pool2[((long)(b * 126 + (H - 1)) * 126 + (W - 1)) * 16 + ch];
    patches[idx] = v;
}

// ---------------- TF32 tensor-core GEMM --------------------------------------
// C = A(MxK) * B(KxN) + bias, optional relu. BM=128, BN=64, BK=32.
// 256 threads = 8 warps (4 m-warps x 2 n-warps), each warp 32x32 via m16n8k8.
// Double-buffered smem; float->tf32 conversion at staging time.
// blockIdx.z selects among three (B, bias, C) triples (fused QKV).

__device__ __forceinline__ uint32_t f2tf32(float x) {
    uint32_t r;
    asm("cvt.rna.tf32.f32 %0, %1;" : "=r"(r) : "f"(x));
    return r;
}

__device__ __forceinline__ void mma_tf32(float* d, const uint32_t* a, const uint32_t* b) {
    asm volatile(
        "mma.sync.aligned.m16n8k8.row.col.f32.tf32.tf32.f32 "
        "{%0,%1,%2,%3}, {%4,%5,%6,%7}, {%8,%9}, {%0,%1,%2,%3};\n"
        : "+f"(d[0]), "+f"(d[1]), "+f"(d[2]), "+f"(d[3])
        : "r"(a[0]), "r"(a[1]), "r"(a[2]), "r"(a[3]), "r"(b[0]), "r"(b[1]));
}

#define AS_STRIDE 36   // (BK=32)+4 pad -> conflict-free frag loads
#define BS_STRIDE 72   // (BN=64)+8 pad
#define AS_TILE   (128 * AS_STRIDE)   // 4608 u32
#define BS_TILE   (32 * BS_STRIDE)    // 2304 u32
#define GEMM_SMEM ((2 * AS_TILE + 2 * BS_TILE) * 4)   // 55296 B

__global__ __launch_bounds__(256) void gemm_tf32_kernel(
    const float* __restrict__ A,
    const float* __restrict__ Bp0, const float* __restrict__ Bp1, const float* __restrict__ Bp2,
    const float* __restrict__ bi0, const float* __restrict__ bi1, const float* __restrict__ bi2,
    float* __restrict__ Cp0, float* __restrict__ Cp1, float* __restrict__ Cp2,
    int M, int N, int K, int relu)
{
    extern __shared__ uint32_t smu[];
    uint32_t* As = smu;                 // 2 buffers, [row][k] row-major, stride 36
    uint32_t* Bs = smu + 2 * AS_TILE;   // 2 buffers, [k][n] row-major, stride 72

    const float* B  = blockIdx.z == 0 ? Bp0 : (blockIdx.z == 1 ? Bp1 : Bp2);
    const float* bi = blockIdx.z == 0 ? bi0 : (blockIdx.z == 1 ? bi1 : bi2);
    float*       C  = blockIdx.z == 0 ? Cp0 : (blockIdx.z == 1 ? Cp1 : Cp2);

    const int tid  = threadIdx.x;
    const int lane = tid & 31;
    const int warp = tid >> 5;
    const int wm   = warp & 3;     // 0..3 -> m offset wm*32
    const int wn   = warp >> 2;    // 0..1 -> n offset wn*32
    const int gid  = lane >> 2;    // 0..7
    const int tkc  = lane & 3;     // 0..3

    const int bm = blockIdx.y * 128;
    const int bn = blockIdx.x * 64;

    // staging mapping
    const int arow  = tid >> 1;          // 0..127
    const int akseg = (tid & 1) << 4;    // 0 or 16
    const int brow  = tid >> 3;          // 0..31
    const int bn0   = (tid & 7) << 3;    // 0..56

    const float* Ag = A + (long)(bm + arow) * K + akseg;
    const float* Bg = B + (long)brow * N + bn + bn0;

    float4 pa[4];
    float4 pb[2];

    // preload tile 0
#pragma unroll
    for (int i = 0; i < 4; i++) pa[i] = *(const float4*)(Ag + i * 4);
    pb[0] = *(const float4*)(Bg);
    pb[1] = *(const float4*)(Bg + 4);

    auto store_tiles = [&](int buf) {
        uint32_t* as = As + buf * AS_TILE + arow * AS_STRIDE + akseg;
#pragma unroll
        for (int i = 0; i < 4; i++) {
            uint32_t* p = as + i * 4;
            p[0] = f2tf32(pa[i].x); p[1] = f2tf32(pa[i].y);
            p[2] = f2tf32(pa[i].z); p[3] = f2tf32(pa[i].w);
        }
        uint32_t* p = Bs + buf * BS_TILE + brow * BS_STRIDE + bn0;
        p[0] = f2tf32(pb[0].x); p[1] = f2tf32(pb[0].y);
        p[2] = f2tf32(pb[0].z); p[3] = f2tf32(pb[0].w);
        p[4] = f2tf32(pb[1].x); p[5] = f2tf32(pb[1].y);
        p[6] = f2tf32(pb[1].z); p[7] = f2tf32(pb[1].w);
    };

    store_tiles(0);
    __syncthreads();

    float acc[2][4][4];
#pragma unroll
    for (int mc = 0; mc < 2; mc++)
#pragma unroll
        for (int nc = 0; nc < 4; nc++)
#pragma unroll
            for (int i = 0; i < 4; i++) acc[mc][nc][i] = 0.0f;

    const int KT = K >> 5;
    for (int kt = 0; kt < KT; kt++) {
        if (kt + 1 < KT) {
            const float* Ag2 = Ag + (kt + 1) * 32;
            const float* Bg2 = Bg + (long)(kt + 1) * 32 * N;
#pragma unroll
            for (int i = 0; i < 4; i++) pa[i] = *(const float4*)(Ag2 + i * 4);
            pb[0] = *(const float4*)(Bg2);
            pb[1] = *(const float4*)(Bg2 + 4);
        }

        const uint32_t* as = As + (kt & 1) * AS_TILE;
        const uint32_t* bs = Bs + (kt & 1) * BS_TILE;

#pragma unroll
        for (int ks = 0; ks < 4; ks++) {
            uint32_t af[2][4], bf[4][2];
            const int kc = ks * 8 + tkc;
#pragma unroll
            for (int mc = 0; mc < 2; mc++) {
                const int r = wm * 32 + mc * 16 + gid;
                af[mc][0] = as[r * AS_STRIDE + kc];
                af[mc][1] = as[(r + 8) * AS_STRIDE + kc];
                af[mc][2] = as[r * AS_STRIDE + kc + 4];
                af[mc][3] = as[(r + 8) * AS_STRIDE + kc + 4];
            }
#pragma unroll
            for (int nc = 0; nc < 4; nc++) {
                const int c = wn * 32 + nc * 8 + gid;
                bf[nc][0] = bs[(ks * 8 + tkc) * BS_STRIDE + c];
                bf[nc][1] = bs[(ks * 8 + tkc + 4) * BS_STRIDE + c];
            }
#pragma unroll
            for (int mc = 0; mc < 2; mc++)
#pragma unroll
                for (int nc = 0; nc < 4; nc++)
                    mma_tf32(acc[mc][nc], af[mc], bf[nc]);
        }

        if (kt + 1 < KT) store_tiles((kt + 1) & 1);
        __syncthreads();
    }

    // epilogue
#pragma unroll
    for (int mc = 0; mc < 2; mc++) {
        const int r0 = bm + wm * 32 + mc * 16 + gid;
#pragma unroll
        for (int nc = 0; nc < 4; nc++) {
            const int col = bn + wn * 32 + nc * 8 + 2 * tkc;
            const float b0 = bi[col], b1 = bi[col + 1];
            float v0 = acc[mc][nc][0] + b0;
            float v1 = acc[mc][nc][1] + b1;
            float v2 = acc[mc][nc][2] + b0;
            float v3 = acc[mc][nc][3] + b1;
            if (relu) {
                v0 = fmaxf(v0, 0.f); v1 = fmaxf(v1, 0.f);
                v2 = fmaxf(v2, 0.f); v3 = fmaxf(v3, 0.f);
            }
            float2 lo = make_float2(v0, v1);
            float2 hi = make_float2(v2, v3);
            *(float2*)&C[(long)r0 * N + col]       = lo;
            *(float2*)&C[(long)(r0 + 8) * N + col] = hi;
        }
    }
}

// ---------------- attention: one block per (b, head) ------------------------
__global__ void attn_kernel(const float* __restrict__ Q,
                            const float* __restrict__ K,
                            const float* __restrict__ V,
                            float* __restrict__ O) {
    extern __shared__ float sm[];
    float* qs = sm;
    float* ks = qs + 64 * 65;
    float* vs = ks + 64 * 65;
    float* ss = vs + 64 * 65;

    int h = blockIdx.x;
    int b = blockIdx.y;
    int tid = threadIdx.x;

    for (int e = tid; e < 4096; e += 256) {
        int s = e >> 6, d = e & 63;
        long base = ((long)(b * 64 + s) * EDIM) + h * 64 + d;
        qs[s * 65 + d] = Q[base];
        ks[s * 65 + d] = K[base];
        vs[s * 65 + d] = V[base];
    }
    __syncthreads();

    for (int e = tid; e < 4096; e += 256) {
        int row = e >> 6, col = e & 63;
        float sum = 0.0f;
#pragma unroll 16
        for (int dd = 0; dd < 64; dd++)
            sum += qs[row * 65 + dd] * ks[col * 65 + dd];
        ss[row * 65 + col] = sum * 0.125f;
    }
    __syncthreads();

    if (tid < 64) {
        float* r = ss + tid * 65;
        float m = r[0];
#pragma unroll 16
        for (int c = 1; c < 64; c++) m = fmaxf(m, r[c]);
        float sum = 0.0f;
#pragma unroll 16
        for (int c = 0; c < 64; c++) { float e = expf(r[c] - m); r[c] = e; sum += e; }
        float inv = 1.0f / sum;
#pragma unroll 16
        for (int c = 0; c < 64; c++) r[c] *= inv;
    }
    __syncthreads();

    for (int e = tid; e < 4096; e += 256) {
        int row = e >> 6, d = e & 63;
        float sum = 0.0f;
#pragma unroll 16
        for (int col = 0; col < 64; col++)
            sum += ss[row * 65 + col] * vs[col * 65 + d];
        O[(long)b * (NHEADS * SEQ * HD) + h * 4096 + row * 64 + d] = sum;
    }
}

// ---------------- add + layernorm (row = 768) -------------------------------
__global__ void add_ln_kernel(const float* __restrict__ x,
                              const float* __restrict__ y,
                              const float* __restrict__ g,
                              const float* __restrict__ be,
                              float* __restrict__ out) {
    __shared__ float buf[EDIM];
    __shared__ float red[256];
    int row = blockIdx.x;
    int tid = threadIdx.x;
    long base = (long)row * EDIM;

    float partial = 0.0f;
    for (int e = tid; e < EDIM; e += 256) {
        float v = x[base + e] + y[base + e];
        buf[e] = v;
        partial += v;
    }
    red[tid] = partial;
    __syncthreads();
    for (int s = 128; s > 0; s >>= 1) {
        if (tid < s) red[tid] += red[tid + s];
        __syncthreads();
    }
    float mean = red[0] * (1.0f / EDIM);
    __syncthreads();

    float p2 = 0.0f;
    for (int e = tid; e < EDIM; e += 256) {
        float d = buf[e] - mean;
        p2 += d * d;
    }
    red[tid] = p2;
    __syncthreads();
    for (int s = 128; s > 0; s >>= 1) {
        if (tid < s) red[tid] += red[tid + s];
        __syncthreads();
    }
    float var = red[0] * (1.0f / EDIM);
    float rstd = rsqrtf(var + 1e-6f);

    for (int e = tid; e < EDIM; e += 256)
        out[base + e] = (buf[e] - mean) * rstd * g[e] + be[e];
}

// ---------------- mean-pool + head + sigmoid --------------------------------
__global__ void head_kernel(const float* __restrict__ t,
                            const float* __restrict__ hw,
                            const float* __restrict__ hb,
                            float* __restrict__ out) {
    __shared__ float red[256];
    int b = blockIdx.x;
    int tid = threadIdx.x;
    float partial = 0.0f;
    for (int e = tid; e < EDIM; e += 256) {
        float se = 0.0f;
        for (int s = 0; s < SEQ; s++)
            se += t[((long)(b * SEQ + s)) * EDIM + e];
        partial += (se * (1.0f / SEQ)) * hw[e];
    }
    red[tid] = partial;
    __syncthreads();
    for (int s = 128; s > 0; s >>= 1) {
        if (tid < s) red[tid] += red[tid + s];
        __syncthreads();
    }
    if (tid == 0) {
        float z = red[0] + hb[0];
        out[b] = 1.0f / (1.0f + expf(-z));
    }
}

// ---------------- host launch ------------------------------------------------
static inline void launch_gemm1(const float* A, const float* B, const float* bias,
                                float* C, int M, int N, int K, int relu) {
    dim3 grid(N / 64, M / 128, 1);
    gemm_tf32_kernel<<<grid, 256, GEMM_SMEM>>>(A, B, B, B, bias, bias, bias,
                                               C, C, C, M, N, K, relu);
}

extern "C" void kernel_launch(void* const* d_in, const int* in_sizes, int n_in,
                              void* d_out, int out_size) {
    const float* x       = (const float*)d_in[0];
    const float* conv1_w = (const float*)d_in[1];
    const float* conv1_b = (const float*)d_in[2];
    const float* conv2_w = (const float*)d_in[3];
    const float* conv2_b = (const float*)d_in[4];
    const float* proj_w  = (const float*)d_in[5];
    const float* proj_b  = (const float*)d_in[6];
    const float* Wq = (const float*)d_in[7];
    const float* bq = (const float*)d_in[8];
    const float* Wk = (const float*)d_in[9];
    const float* bk = (const float*)d_in[10];
    const float* Wv = (const float*)d_in[11];
    const float* bv = (const float*)d_in[12];
    const float* Wo = (const float*)d_in[13];
    const float* bo = (const float*)d_in[14];
    const float* W1 = (const float*)d_in[15];
    const float* b1 = (const float*)d_in[16];
    const float* W2 = (const float*)d_in[17];
    const float* b2 = (const float*)d_in[18];
    const float* ln1_g = (const float*)d_in[19];
    const float* ln1_b = (const float*)d_in[20];
    const float* ln2_g = (const float*)d_in[21];
    const float* ln2_b = (const float*)d_in[22];
    const float* head_w = (const float*)d_in[23];
    const float* head_b = (const float*)d_in[24];
    float* out = (float*)d_out;

    float *pool1, *pool2, *patches, *t, *q, *k, *v, *att, *a2, *o1, *f1, *f2;
    cudaGetSymbolAddress((void**)&pool1, g_pool1);
    cudaGetSymbolAddress((void**)&pool2, g_pool2);
    cudaGetSymbolAddress((void**)&patches, g_patches);
    cudaGetSymbolAddress((void**)&t,  g_t);
    cudaGetSymbolAddress((void**)&q,  g_q);
    cudaGetSymbolAddress((void**)&k,  g_k);
    cudaGetSymbolAddress((void**)&v,  g_v);
    cudaGetSymbolAddress((void**)&att, g_att);
    cudaGetSymbolAddress((void**)&a2, g_a2);
    cudaGetSymbolAddress((void**)&o1, g_o1);
    cudaGetSymbolAddress((void**)&f1, g_f1);
    cudaGetSymbolAddress((void**)&f2, g_f2);

    const int attn_smem = 4 * 64 * 65 * sizeof(float);
    cudaFuncSetAttribute(attn_kernel, cudaFuncAttributeMaxDynamicSharedMemorySize, attn_smem);
    cudaFuncSetAttribute(gemm_tf32_kernel, cudaFuncAttributeMaxDynamicSharedMemorySize, GEMM_SMEM);

    // conv stack
    {
        int n1 = 16 * 255 * 255;
        conv1_pool_kernel<<<(n1 + 255) / 256, 256>>>(x, conv1_w, conv1_b, pool1);
        int n2 = 16 * 126 * 126;
        conv2_pool_kernel<<<(n2 + 255) / 256, 256>>>(pool1, conv2_w, conv2_b, pool2);
        long np = (long)ROWSM * PDIM;
        patch_kernel<<<(int)((np + 255) / 256), 256>>>(pool2, patches);
    }

    // patch projection
    launch_gemm1(patches, proj_w, proj_b, t, ROWSM, EDIM, PDIM, 0);

    for (int i = 0; i < NLAYER; i++) {
        const float* wq = Wq + (long)i * EDIM * EDIM;
        const float* wk = Wk + (long)i * EDIM * EDIM;
        const float* wv = Wv + (long)i * EDIM * EDIM;
        const float* wo = Wo + (long)i * EDIM * EDIM;
        const float* w1 = W1 + (long)i * EDIM * FFDIM;
        const float* w2 = W2 + (long)i * FFDIM * EDIM;

        // fused QKV: one launch, gridDim.z = 3
        {
            dim3 grid(EDIM / 64, ROWSM / 128, 3);
            gemm_tf32_kernel<<<grid, 256, GEMM_SMEM>>>(
                t, wq, wk, wv,
                bq + i * EDIM, bk + i * EDIM, bv + i * EDIM,
                q, k, v, ROWSM, EDIM, EDIM, 0);
        }

        attn_kernel<<<dim3(NHEADS, BB), 256, attn_smem>>>(q, k, v, att);

        launch_gemm1(att, wo, bo + i * EDIM, a2, ROWSM, EDIM, EDIM, 0);
        add_ln_kernel<<<ROWSM, 256>>>(t, a2, ln1_g + i * EDIM, ln1_b + i * EDIM, o1);
        launch_gemm1(o1, w1, b1 + i * FFDIM, f1, ROWSM, FFDIM, EDIM, 1);
        launch_gemm1(f1, w2, b2 + i * EDIM, f2, ROWSM, EDIM, FFDIM, 0);
        add_ln_kernel<<<ROWSM, 256>>>(o1, f2, ln2_g + i * EDIM, ln2_b + i * EDIM, t);
    }

    head_kernel<<<BB, 256>>>(t, head_w, head_b, out);
}

// round 3
// speedup vs baseline: 2.5906x; 1.4086x over previous
#include <cuda_runtime.h>
#include <math.h>
#include <stdint.h>

// ---------------- model constants ----------------
#define BB     16
#define EDIM   768
#define NHEADS 12
#define HD     64
#define FFDIM  3072
#define NLAYER 8
#define SEQ    64
#define ROWSM  1024     // BB*SEQ
#define PDIM   4096

// ---------------- scratch (device globals; no allocations allowed) ----------
__device__ float g_pool1[16 * 255 * 255 * 16];
__device__ float g_pool2[16 * 126 * 126 * 16];
__device__ float g_patches[ROWSM * PDIM];
__device__ float g_t [ROWSM * EDIM];
__device__ float g_q [ROWSM * EDIM];
__device__ float g_k [ROWSM * EDIM];
__device__ float g_v [ROWSM * EDIM];
__device__ float g_att[ROWSM * EDIM];
__device__ float g_a2[ROWSM * EDIM];
__device__ float g_o1[ROWSM * EDIM];
__device__ float g_f1[ROWSM * FFDIM];
__device__ float g_f2[ROWSM * EDIM];
__device__ float g_part[3 * ROWSM * FFDIM];   // split-K partials (max 3 x 1024 x 3072)

// ---------------- conv1 (3x3x3->16) + relu + maxpool2x2, fused -------------
__global__ void conv1_pool_kernel(const float* __restrict__ x,
                                  const float* __restrict__ w,
                                  const float* __restrict__ bias,
                                  float* __restrict__ out) {
    __shared__ float ws[432];
    __shared__ float bs[16];
    int tid = threadIdx.x;
    for (int i = tid; i < 432; i += 256) ws[i] = w[i];
    if (tid < 16) bs[tid] = bias[tid];
    __syncthreads();

    int idx = blockIdx.x * 256 + tid;
    if (idx >= 16 * 255 * 255) return;
    int pw = idx % 255;
    int t  = idx / 255;
    int ph = t % 255;
    int b  = t / 255;

    float mx[16];
#pragma unroll
    for (int c = 0; c < 16; c++) mx[c] = 0.0f;

    for (int dy = 0; dy < 2; dy++) {
        for (int dx = 0; dx < 2; dx++) {
            int h0 = 2 * ph + dy;
            int w0 = 2 * pw + dx;
            float acc[16];
#pragma unroll
            for (int c = 0; c < 16; c++) acc[c] = bs[c];
            for (int kh = 0; kh < 3; kh++) {
                for (int kw = 0; kw < 3; kw++) {
                    const float* xp = x + (((long)(b * 512 + h0 + kh) * 512) + (w0 + kw)) * 3;
                    float x0 = xp[0], x1 = xp[1], x2 = xp[2];
                    const float* wp = ws + ((kh * 3 + kw) * 3) * 16;
#pragma unroll
                    for (int c = 0; c < 16; c++)
                        acc[c] += x0 * wp[c] + x1 * wp[16 + c] + x2 * wp[32 + c];
                }
            }
#pragma unroll
            for (int c = 0; c < 16; c++) mx[c] = fmaxf(mx[c], fmaxf(acc[c], 0.0f));
        }
    }
    float* op = out + (long)idx * 16;
#pragma unroll
    for (int c = 0; c < 16; c++) op[c] = mx[c];
}

// ---------------- conv2 (3x3x16->16) + relu + maxpool2x2, fused ------------
__global__ void conv2_pool_kernel(const float* __restrict__ in,
                                  const float* __restrict__ w,
                                  const float* __restrict__ bias,
                                  float* __restrict__ out) {
    __shared__ float ws[2304];
    __shared__ float bs[16];
    int tid = threadIdx.x;
    for (int i = tid; i < 2304; i += 256) ws[i] = w[i];
    if (tid < 16) bs[tid] = bias[tid];
    __syncthreads();

    int idx = blockIdx.x * 256 + tid;
    if (idx >= 16 * 126 * 126) return;
    int pw = idx % 126;
    int t  = idx / 126;
    int ph = t % 126;
    int b  = t / 126;

    float mx[16];
#pragma unroll
    for (int c = 0; c < 16; c++) mx[c] = 0.0f;

    for (int dy = 0; dy < 2; dy++) {
        for (int dx = 0; dx < 2; dx++) {
            int h0 = 2 * ph + dy;
            int w0 = 2 * pw + dx;
            float acc[16];
#pragma unroll
            for (int c = 0; c < 16; c++) acc[c] = bs[c];
            for (int kh = 0; kh < 3; kh++) {
                for (int kw = 0; kw < 3; kw++) {
                    const float* xp = in + ((long)(b * 255 + h0 + kh) * 255 + (w0 + kw)) * 16;
                    float xv[16];
#pragma unroll
                    for (int ci = 0; ci < 16; ci++) xv[ci] = xp[ci];
                    const float* wp = ws + ((kh * 3 + kw) * 16) * 16;
#pragma unroll
                    for (int ci = 0; ci < 16; ci++) {
#pragma unroll
                        for (int c = 0; c < 16; c++)
                            acc[c] += xv[ci] * wp[ci * 16 + c];
                    }
                }
            }
#pragma unroll
            for (int c = 0; c < 16; c++) mx[c] = fmaxf(mx[c], fmaxf(acc[c], 0.0f));
        }
    }
    float* op = out + (long)idx * 16;
#pragma unroll
    for (int c = 0; c < 16; c++) op[c] = mx[c];
}

// ---------------- patch gather -----------------------------------------------
__global__ void patch_kernel(const float* __restrict__ pool2,
                             float* __restrict__ patches) {
    long idx = (long)blockIdx.x * 256 + threadIdx.x;
    if (idx >= (long)ROWSM * PDIM) return;
    int d   = (int)(idx & (PDIM - 1));
    int row = (int)(idx >> 12);
    int b   = row >> 6;
    int p   = row & 63;
    int pr  = p >> 3, pc = p & 7;
    int r   = d >> 8;
    int c   = (d >> 4) & 15;
    int ch  = d & 15;
    int H = pr * 16 + r;
    int W = pc * 16 + c;
    float v = 0.0f;
    if (H >= 1 && H <= 126 && W >= 1 && W <= 126)
        v = pool2[((long)(b * 126 + (H - 1)) * 126 + (W - 1)) * 16 + ch];
    patches[idx] = v;
}

// ---------------- TF32 tensor-core GEMM, cp.async 4-stage pipeline ----------
// C = A(MxK) * B(KxN) + bias (+relu).  BM=128, BN=128, BK=32.
// 256 threads = 8 warps (4 m x 2 n), warp tile 32x64 via m16n8k8.
// fp32 bits fed directly as tf32 (HW truncates; CUTLASS fast-tf32 path).
// blockIdx.z = mat * splitk + kz. Multi-mat only with splitk==1 (QKV).
// splitk>1 writes raw partials to `part` (reduced by splitk_reduce_kernel).

__device__ __forceinline__ void mma_tf32(float* d, const uint32_t* a, const uint32_t* b) {
    asm volatile(
        "mma.sync.aligned.m16n8k8.row.col.f32.tf32.tf32.f32 "
        "{%0,%1,%2,%3}, {%4,%5,%6,%7}, {%8,%9}, {%0,%1,%2,%3};\n"
        : "+f"(d[0]), "+f"(d[1]), "+f"(d[2]), "+f"(d[3])
        : "r"(a[0]), "r"(a[1]), "r"(a[2]), "r"(a[3]), "r"(b[0]), "r"(b[1]));
}

__device__ __forceinline__ void cp16(void* sdst, const void* gsrc) {
    uint32_t s = (uint32_t)__cvta_generic_to_shared(sdst);
    asm volatile("cp.async.cg.shared.global [%0], [%1], 16;\n" :: "r"(s), "l"(gsrc));
}
__device__ __forceinline__ void cp_commit() { asm volatile("cp.async.commit_group;\n"); }
template <int N> __device__ __forceinline__ void cp_wait() {
    asm volatile("cp.async.wait_group %0;\n" :: "n"(N));
}

#define ASTR 36                 // u32 per A row (32 + 4 pad), 144B (16B aligned)
#define BSTR 136                // u32 per B k-row (128 + 8 pad), 544B
#define AS_TILE (128 * ASTR)    // 4608 u32
#define BS_TILE (32 * BSTR)     // 4352 u32
#define STAGE_U32 (AS_TILE + BS_TILE)            // 8960 u32
#define GEMM_SMEM (4 * STAGE_U32 * 4)            // 143360 B

__global__ __launch_bounds__(256, 1) void gemm_tf32_kernel(
    const float* __restrict__ A,
    const float* __restrict__ Bp0, const float* __restrict__ Bp1, const float* __restrict__ Bp2,
    const float* __restrict__ bi0, const float* __restrict__ bi1, const float* __restrict__ bi2,
    float* __restrict__ Cp0, float* __restrict__ Cp1, float* __restrict__ Cp2,
    float* __restrict__ part,
    int M, int N, int K, int splitk, int relu)
{
    extern __shared__ uint32_t smu[];

    const int z   = blockIdx.z;
    const int mat = z / splitk;
    const int kz  = z - mat * splitk;
    const float* B  = mat == 0 ? Bp0 : (mat == 1 ? Bp1 : Bp2);
    const float* bi = mat == 0 ? bi0 : (mat == 1 ? bi1 : bi2);
    float*       C  = mat == 0 ? Cp0 : (mat == 1 ? Cp1 : Cp2);

    const int tid  = threadIdx.x;
    const int lane = tid & 31;
    const int warp = tid >> 5;
    const int wm   = warp & 3;      // row group (32 rows)
    const int wn   = warp >> 2;     // col group (64 cols)
    const int gid  = lane >> 2;
    const int tkc  = lane & 3;

    const int bm = blockIdx.y * 128;
    const int bn = blockIdx.x * 128;

    const int ktot = K >> 5;
    const int ktb  = (kz * ktot) / splitk;
    const int kte  = ((kz + 1) * ktot) / splitk;
    const int nkt  = kte - ktb;

    auto issue = [&](int i) {
        uint32_t* As = smu + (i & 3) * STAGE_U32;
        uint32_t* Bs = As + AS_TILE;
        long k0 = (long)(ktb + i) * 32;
#pragma unroll
        for (int t = 0; t < 4; t++) {
            int id = tid + t * 256;
            int row = id >> 3, seg = (id & 7) * 4;
            cp16(As + row * ASTR + seg, A + (long)(bm + row) * K + k0 + seg);
        }
#pragma unroll
        for (int t = 0; t < 4; t++) {
            int id = tid + t * 256;
            int row = id >> 5, seg = (id & 31) * 4;
            cp16(Bs + row * BSTR + seg, B + (k0 + row) * (long)N + bn + seg);
        }
    };

    const int P = nkt < 3 ? nkt : 3;
    for (int i = 0; i < P; i++) { issue(i); cp_commit(); }

    float acc[2][8][4];
#pragma unroll
    for (int mc = 0; mc < 2; mc++)
#pragma unroll
        for (int nc = 0; nc < 8; nc++)
#pragma unroll
            for (int i = 0; i < 4; i++) acc[mc][nc][i] = 0.0f;

    for (int i = 0; i < nkt; i++) {
        cp_wait<2>();
        __syncthreads();
        if (i + 3 < nkt) issue(i + 3);
        cp_commit();

        const uint32_t* as = smu + (i & 3) * STAGE_U32;
        const uint32_t* bs = as + AS_TILE;

#pragma unroll
        for (int ks = 0; ks < 4; ks++) {
            const int kc = ks * 8 + tkc;
            uint32_t af[2][4];
#pragma unroll
            for (int mc = 0; mc < 2; mc++) {
                const int r = wm * 32 + mc * 16 + gid;
                af[mc][0] = as[r * ASTR + kc];
                af[mc][1] = as[(r + 8) * ASTR + kc];
                af[mc][2] = as[r * ASTR + kc + 4];
                af[mc][3] = as[(r + 8) * ASTR + kc + 4];
            }
#pragma unroll
            for (int nc = 0; nc < 8; nc++) {
                uint32_t bf[2];
                const int c = wn * 64 + nc * 8 + gid;
                bf[0] = bs[kc * BSTR + c];
                bf[1] = bs[(kc + 4) * BSTR + c];
                mma_tf32(acc[0][nc], af[0], bf);
                mma_tf32(acc[1][nc], af[1], bf);
            }
        }
    }

    // epilogue
    if (splitk == 1) {
#pragma unroll
        for (int mc = 0; mc < 2; mc++) {
            const int r0 = bm + wm * 32 + mc * 16 + gid;
#pragma unroll
            for (int nc = 0; nc < 8; nc++) {
                const int col = bn + wn * 64 + nc * 8 + 2 * tkc;
                const float b0 = bi[col], b1 = bi[col + 1];
                float v0 = acc[mc][nc][0] + b0;
                float v1 = acc[mc][nc][1] + b1;
                float v2 = acc[mc][nc][2] + b0;
                float v3 = acc[mc][nc][3] + b1;
                if (relu) {
                    v0 = fmaxf(v0, 0.f); v1 = fmaxf(v1, 0.f);
                    v2 = fmaxf(v2, 0.f); v3 = fmaxf(v3, 0.f);
                }
                *(float2*)&C[(long)r0 * N + col]       = make_float2(v0, v1);
                *(float2*)&C[(long)(r0 + 8) * N + col] = make_float2(v2, v3);
            }
        }
    } else {
        float* P0 = part + (long)kz * M * N;
#pragma unroll
        for (int mc = 0; mc < 2; mc++) {
            const int r0 = bm + wm * 32 + mc * 16 + gid;
#pragma unroll
            for (int nc = 0; nc < 8; nc++) {
                const int col = bn + wn * 64 + nc * 8 + 2 * tkc;
                *(float2*)&P0[(long)r0 * N + col]       = make_float2(acc[mc][nc][0], acc[mc][nc][1]);
                *(float2*)&P0[(long)(r0 + 8) * N + col] = make_float2(acc[mc][nc][2], acc[mc][nc][3]);
            }
        }
    }
}

// ordered, deterministic split-K reduce + bias (+relu)
__global__ void splitk_reduce_kernel(const float* __restrict__ part,
                                     const float* __restrict__ bias,
                                     float* __restrict__ C,
                                     int MN, int N, int splitk, int relu) {
    int idx = blockIdx.x * 256 + threadIdx.x;
    if (idx >= MN) return;
    float s = part[idx];
    for (int z = 1; z < splitk; z++) s += part[(long)z * MN + idx];
    s += bias[idx % N];
    if (relu) s = fmaxf(s, 0.0f);
    C[idx] = s;
}

// ---------------- attention: one block per (b, head) ------------------------
__global__ void attn_kernel(const float* __restrict__ Q,
                            const float* __restrict__ K,
                            const float* __restrict__ V,
                            float* __restrict__ O) {
    extern __shared__ float sm[];
    float* qs = sm;
    float* ks = qs + 64 * 65;
    float* vs = ks + 64 * 65;
    float* ss = vs + 64 * 65;

    int h = blockIdx.x;
    int b = blockIdx.y;
    int tid = threadIdx.x;

    for (int e = tid; e < 4096; e += 256) {
        int s = e >> 6, d = e & 63;
        long base = ((long)(b * 64 + s) * EDIM) + h * 64 + d;
        qs[s * 65 + d] = Q[base];
        ks[s * 65 + d] = K[base];
        vs[s * 65 + d] = V[base];
    }
    __syncthreads();

    for (int e = tid; e < 4096; e += 256) {
        int row = e >> 6, col = e & 63;
        float sum = 0.0f;
#pragma unroll 16
        for (int dd = 0; dd < 64; dd++)
            sum += qs[row * 65 + dd] * ks[col * 65 + dd];
        ss[row * 65 + col] = sum * 0.125f;
    }
    __syncthreads();

    if (tid < 64) {
        float* r = ss + tid * 65;
        float m = r[0];
#pragma unroll 16
        for (int c = 1; c < 64; c++) m = fmaxf(m, r[c]);
        float sum = 0.0f;
#pragma unroll 16
        for (int c = 0; c < 64; c++) { float e = expf(r[c] - m); r[c] = e; sum += e; }
        float inv = 1.0f / sum;
#pragma unroll 16
        for (int c = 0; c < 64; c++) r[c] *= inv;
    }
    __syncthreads();

    for (int e = tid; e < 4096; e += 256) {
        int row = e >> 6, d = e & 63;
        float sum = 0.0f;
#pragma unroll 16
        for (int col = 0; col < 64; col++)
            sum += ss[row * 65 + col] * vs[col * 65 + d];
        O[(long)b * (NHEADS * SEQ * HD) + h * 4096 + row * 64 + d] = sum;
    }
}

// ---------------- add + layernorm (row = 768) -------------------------------
__global__ void add_ln_kernel(const float* __restrict__ x,
                              const float* __restrict__ y,
                              const float* __restrict__ g,
                              const float* __restrict__ be,
                              float* __restrict__ out) {
    __shared__ float buf[EDIM];
    __shared__ float red[256];
    int row = blockIdx.x;
    int tid = threadIdx.x;
    long base = (long)row * EDIM;

    float partial = 0.0f;
    for (int e = tid; e < EDIM; e += 256) {
        float v = x[base + e] + y[base + e];
        buf[e] = v;
        partial += v;
    }
    red[tid] = partial;
    __syncthreads();
    for (int s = 128; s > 0; s >>= 1) {
        if (tid < s) red[tid] += red[tid + s];
        __syncthreads();
    }
    float mean = red[0] * (1.0f / EDIM);
    __syncthreads();

    float p2 = 0.0f;
    for (int e = tid; e < EDIM; e += 256) {
        float d = buf[e] - mean;
        p2 += d * d;
    }
    red[tid] = p2;
    __syncthreads();
    for (int s = 128; s > 0; s >>= 1) {
        if (tid < s) red[tid] += red[tid + s];
        __syncthreads();
    }
    float var = red[0] * (1.0f / EDIM);
    float rstd = rsqrtf(var + 1e-6f);

    for (int e = tid; e < EDIM; e += 256)
        out[base + e] = (buf[e] - mean) * rstd * g[e] + be[e];
}

// ---------------- mean-pool + head + sigmoid --------------------------------
__global__ void head_kernel(const float* __restrict__ t,
                            const float* __restrict__ hw,
                            const float* __restrict__ hb,
                            float* __restrict__ out) {
    __shared__ float red[256];
    int b = blockIdx.x;
    int tid = threadIdx.x;
    float partial = 0.0f;
    for (int e = tid; e < EDIM; e += 256) {
        float se = 0.0f;
        for (int s = 0; s < SEQ; s++)
            se += t[((long)(b * SEQ + s)) * EDIM + e];
        partial += (se * (1.0f / SEQ)) * hw[e];
    }
    red[tid] = partial;
    __syncthreads();
    for (int s = 128; s > 0; s >>= 1) {
        if (tid < s) red[tid] += red[tid + s];
        __syncthreads();
    }
    if (tid == 0) {
        float z = red[0] + hb[0];
        out[b] = 1.0f / (1.0f + expf(-z));
    }
}

// ---------------- host launch ------------------------------------------------
static inline void launch_gemm(const float* A, const float* B, const float* bias,
                               float* C, float* part,
                               int M, int N, int K, int splitk, int relu) {
    dim3 grid(N / 128, M / 128, splitk);
    gemm_tf32_kernel<<<grid, 256, GEMM_SMEM>>>(A, B, B, B, bias, bias, bias,
                                               C, C, C, part, M, N, K, splitk, relu);
    if (splitk > 1) {
        int MN = M * N;
        splitk_reduce_kernel<<<(MN + 255) / 256, 256>>>(part, bias, C, MN, N, splitk, relu);
    }
}

extern "C" void kernel_launch(void* const* d_in, const int* in_sizes, int n_in,
                              void* d_out, int out_size) {
    const float* x       = (const float*)d_in[0];
    const float* conv1_w = (const float*)d_in[1];
    const float* conv1_b = (const float*)d_in[2];
    const float* conv2_w = (const float*)d_in[3];
    const float* conv2_b = (const float*)d_in[4];
    const float* proj_w  = (const float*)d_in[5];
    const float* proj_b  = (const float*)d_in[6];
    const float* Wq = (const float*)d_in[7];
    const float* bq = (const float*)d_in[8];
    const float* Wk = (const float*)d_in[9];
    const float* bk = (const float*)d_in[10];
    const float* Wv = (const float*)d_in[11];
    const float* bv = (const float*)d_in[12];
    const float* Wo = (const float*)d_in[13];
    const float* bo = (const float*)d_in[14];
    const float* W1 = (const float*)d_in[15];
    const float* b1 = (const float*)d_in[16];
    const float* W2 = (const float*)d_in[17];
    const float* b2 = (const float*)d_in[18];
    const float* ln1_g = (const float*)d_in[19];
    const float* ln1_b = (const float*)d_in[20];
    const float* ln2_g = (const float*)d_in[21];
    const float* ln2_b = (const float*)d_in[22];
    const float* head_w = (const float*)d_in[23];
    const float* head_b = (const float*)d_in[24];
    float* out = (float*)d_out;

    float *pool1, *pool2, *patches, *t, *q, *k, *v, *att, *a2, *o1, *f1, *f2, *part;
    cudaGetSymbolAddress((void**)&pool1, g_pool1);
    cudaGetSymbolAddress((void**)&pool2, g_pool2);
    cudaGetSymbolAddress((void**)&patches, g_patches);
    cudaGetSymbolAddress((void**)&t,  g_t);
    cudaGetSymbolAddress((void**)&q,  g_q);
    cudaGetSymbolAddress((void**)&k,  g_k);
    cudaGetSymbolAddress((void**)&v,  g_v);
    cudaGetSymbolAddress((void**)&att, g_att);
    cudaGetSymbolAddress((void**)&a2, g_a2);
    cudaGetSymbolAddress((void**)&o1, g_o1);
    cudaGetSymbolAddress((void**)&f1, g_f1);
    cudaGetSymbolAddress((void**)&f2, g_f2);
    cudaGetSymbolAddress((void**)&part, g_part);

    const int attn_smem = 4 * 64 * 65 * sizeof(float);
    cudaFuncSetAttribute(attn_kernel, cudaFuncAttributeMaxDynamicSharedMemorySize, attn_smem);
    cudaFuncSetAttribute(gemm_tf32_kernel, cudaFuncAttributeMaxDynamicSharedMemorySize, GEMM_SMEM);

    // conv stack
    {
        int n1 = 16 * 255 * 255;
        conv1_pool_kernel<<<(n1 + 255) / 256, 256>>>(x, conv1_w, conv1_b, pool1);
        int n2 = 16 * 126 * 126;
        conv2_pool_kernel<<<(n2 + 255) / 256, 256>>>(pool1, conv2_w, conv2_b, pool2);
        long np = (long)ROWSM * PDIM;
        patch_kernel<<<(int)((np + 255) / 256), 256>>>(pool2, patches);
    }

    // patch projection (K=4096, splitk=3 -> 144 blocks)
    launch_gemm(patches, proj_w, proj_b, t, part, ROWSM, EDIM, PDIM, 3, 0);

    for (int i = 0; i < NLAYER; i++) {
        const float* wq = Wq + (long)i * EDIM * EDIM;
        const float* wk = Wk + (long)i * EDIM * EDIM;
        const float* wv = Wv + (long)i * EDIM * EDIM;
        const float* wo = Wo + (long)i * EDIM * EDIM;
        const float* w1 = W1 + (long)i * EDIM * FFDIM;
        const float* w2 = W2 + (long)i * FFDIM * EDIM;

        // fused QKV: 6x8x3 = 144 blocks, one wave
        {
            dim3 grid(EDIM / 128, ROWSM / 128, 3);
            gemm_tf32_kernel<<<grid, 256, GEMM_SMEM>>>(
                t, wq, wk, wv,
                bq + i * EDIM, bk + i * EDIM, bv + i * EDIM,
                q, k, v, part, ROWSM, EDIM, EDIM, 1, 0);
        }

        attn_kernel<<<dim3(NHEADS, BB), 256, attn_smem>>>(q, k, v, att);

        launch_gemm(att, wo, bo + i * EDIM, a2, part, ROWSM, EDIM, EDIM, 3, 0);
        add_ln_kernel<<<ROWSM, 256>>>(t, a2, ln1_g + i * EDIM, ln1_b + i * EDIM, o1);
        launch_gemm(o1, w1, b1 + i * FFDIM, f1, part, ROWSM, FFDIM, EDIM, 3, 1);
        launch_gemm(f1, w2, b2 + i * EDIM, f2, part, ROWSM, EDIM, FFDIM, 3, 0);
        add_ln_kernel<<<ROWSM, 256>>>(o1, f2, ln2_g + i * EDIM, ln2_b + i * EDIM, t);
    }

    head_kernel<<<BB, 256>>>(t, head_w, head_b, out);
}

// round 4
// speedup vs baseline: 2.7557x; 1.0637x over previous
#include <cuda_runtime.h>
#include <math.h>
#include <stdint.h>

// ---------------- model constants ----------------
#define BB     16
#define EDIM   768
#define NHEADS 12
#define HD     64
#define FFDIM  3072
#define NLAYER 8
#define SEQ    64
#define ROWSM  1024     // BB*SEQ
#define PDIM   4096

// ---------------- scratch (device globals; no allocations allowed) ----------
__device__ float g_pool1[16 * 255 * 255 * 16];
__device__ float g_pool2[16 * 126 * 126 * 16];
__device__ float g_patches[ROWSM * PDIM];
__device__ float g_t [ROWSM * EDIM];
__device__ float g_q [ROWSM * EDIM];
__device__ float g_k [ROWSM * EDIM];
__device__ float g_v [ROWSM * EDIM];
__device__ float g_att[ROWSM * EDIM];
__device__ float g_a2[ROWSM * EDIM];
__device__ float g_o1[ROWSM * EDIM];
__device__ float g_f1[ROWSM * FFDIM];
__device__ float g_f2[ROWSM * EDIM];
__device__ float g_part[3 * ROWSM * FFDIM];   // split-K partials

// ---------------- conv1 (3x3x3->16) + relu + maxpool2x2, fused -------------
__global__ void conv1_pool_kernel(const float* __restrict__ x,
                                  const float* __restrict__ w,
                                  const float* __restrict__ bias,
                                  float* __restrict__ out) {
    __shared__ float ws[432];
    __shared__ float bs[16];
    int tid = threadIdx.x;
    for (int i = tid; i < 432; i += 256) ws[i] = w[i];
    if (tid < 16) bs[tid] = bias[tid];
    __syncthreads();

    int idx = blockIdx.x * 256 + tid;
    if (idx >= 16 * 255 * 255) return;
    int pw = idx % 255;
    int t  = idx / 255;
    int ph = t % 255;
    int b  = t / 255;

    float mx[16];
#pragma unroll
    for (int c = 0; c < 16; c++) mx[c] = 0.0f;

    for (int dy = 0; dy < 2; dy++) {
        for (int dx = 0; dx < 2; dx++) {
            int h0 = 2 * ph + dy;
            int w0 = 2 * pw + dx;
            float acc[16];
#pragma unroll
            for (int c = 0; c < 16; c++) acc[c] = bs[c];
            for (int kh = 0; kh < 3; kh++) {
                for (int kw = 0; kw < 3; kw++) {
                    const float* xp = x + (((long)(b * 512 + h0 + kh) * 512) + (w0 + kw)) * 3;
                    float x0 = xp[0], x1 = xp[1], x2 = xp[2];
                    const float* wp = ws + ((kh * 3 + kw) * 3) * 16;
#pragma unroll
                    for (int c = 0; c < 16; c++)
                        acc[c] += x0 * wp[c] + x1 * wp[16 + c] + x2 * wp[32 + c];
                }
            }
#pragma unroll
            for (int c = 0; c < 16; c++) mx[c] = fmaxf(mx[c], fmaxf(acc[c], 0.0f));
        }
    }
    float* op = out + (long)idx * 16;
#pragma unroll
    for (int c = 0; c < 16; c++) op[c] = mx[c];
}

// ---------------- conv2 (3x3x16->16) + relu + maxpool2x2, fused ------------
__global__ void conv2_pool_kernel(const float* __restrict__ in,
                                  const float* __restrict__ w,
                                  const float* __restrict__ bias,
                                  float* __restrict__ out) {
    __shared__ float ws[2304];
    __shared__ float bs[16];
    int tid = threadIdx.x;
    for (int i = tid; i < 2304; i += 256) ws[i] = w[i];
    if (tid < 16) bs[tid] = bias[tid];
    __syncthreads();

    int idx = blockIdx.x * 256 + tid;
    if (idx >= 16 * 126 * 126) return;
    int pw = idx % 126;
    int t  = idx / 126;
    int ph = t % 126;
    int b  = t / 126;

    float mx[16];
#pragma unroll
    for (int c = 0; c < 16; c++) mx[c] = 0.0f;

    for (int dy = 0; dy < 2; dy++) {
        for (int dx = 0; dx < 2; dx++) {
            int h0 = 2 * ph + dy;
            int w0 = 2 * pw + dx;
            float acc[16];
#pragma unroll
            for (int c = 0; c < 16; c++) acc[c] = bs[c];
            for (int kh = 0; kh < 3; kh++) {
                for (int kw = 0; kw < 3; kw++) {
                    const float* xp = in + ((long)(b * 255 + h0 + kh) * 255 + (w0 + kw)) * 16;
                    float xv[16];
#pragma unroll
                    for (int ci = 0; ci < 16; ci++) xv[ci] = xp[ci];
                    const float* wp = ws + ((kh * 3 + kw) * 16) * 16;
#pragma unroll
                    for (int ci = 0; ci < 16; ci++) {
#pragma unroll
                        for (int c = 0; c < 16; c++)
                            acc[c] += xv[ci] * wp[ci * 16 + c];
                    }
                }
            }
#pragma unroll
            for (int c = 0; c < 16; c++) mx[c] = fmaxf(mx[c], fmaxf(acc[c], 0.0f));
        }
    }
    float* op = out + (long)idx * 16;
#pragma unroll
    for (int c = 0; c < 16; c++) op[c] = mx[c];
}

// ---------------- patch gather -----------------------------------------------
__global__ void patch_kernel(const float* __restrict__ pool2,
                             float* __restrict__ patches) {
    long idx = (long)blockIdx.x * 256 + threadIdx.x;
    if (idx >= (long)ROWSM * PDIM) return;
    int d   = (int)(idx & (PDIM - 1));
    int row = (int)(idx >> 12);
    int b   = row >> 6;
    int p   = row & 63;
    int pr  = p >> 3, pc = p & 7;
    int r   = d >> 8;
    int c   = (d >> 4) & 15;
    int ch  = d & 15;
    int H = pr * 16 + r;
    int W = pc * 16 + c;
    float v = 0.0f;
    if (H >= 1 && H <= 126 && W >= 1 && W <= 126)
        v = pool2[((long)(b * 126 + (H - 1)) * 126 + (W - 1)) * 16 + ch];
    patches[idx] = v;
}

// ---------------- TF32 tensor-core GEMM, cp.async 3-stage, 2 CTA/SM ---------
// C = A(MxK) * B(KxN) + bias (+relu).  BM=128, BN=128, BK=32.
// 256 threads = 8 warps (4 m x 2 n), warp tile 32x64 via m16n8k8.
// fp32 bits fed directly as tf32 (HW truncates).
// blockIdx.z = mat * splitk + kz. Multi-mat only with splitk==1 (QKV).
// splitk>1 writes raw partials to `part`.  NOTE: requires nkt >= 2.

__device__ __forceinline__ void mma_tf32(float* d, const uint32_t* a, const uint32_t* b) {
    asm volatile(
        "mma.sync.aligned.m16n8k8.row.col.f32.tf32.tf32.f32 "
        "{%0,%1,%2,%3}, {%4,%5,%6,%7}, {%8,%9}, {%0,%1,%2,%3};\n"
        : "+f"(d[0]), "+f"(d[1]), "+f"(d[2]), "+f"(d[3])
        : "r"(a[0]), "r"(a[1]), "r"(a[2]), "r"(a[3]), "r"(b[0]), "r"(b[1]));
}

__device__ __forceinline__ void cp16s(uint32_t saddr, const void* gsrc) {
    asm volatile("cp.async.cg.shared.global [%0], [%1], 16;\n" :: "r"(saddr), "l"(gsrc));
}
__device__ __forceinline__ void cp_commit() { asm volatile("cp.async.commit_group;\n"); }
template <int N> __device__ __forceinline__ void cp_wait() {
    asm volatile("cp.async.wait_group %0;\n" :: "n"(N));
}

#define ASTR 36                 // u32 per A row (32 + 4 pad)
#define BSTR 136                // u32 per B k-row (128 + 8 pad)
#define AS_TILE (128 * ASTR)    // 4608 u32
#define BS_TILE (32 * BSTR)     // 4352 u32
#define STAGE_U32 (AS_TILE + BS_TILE)            // 8960 u32
#define NSTAGE 3
#define GEMM_SMEM (NSTAGE * STAGE_U32 * 4)       // 107520 B

__global__ __launch_bounds__(256, 2) void gemm_tf32_kernel(
    const float* __restrict__ A,
    const float* __restrict__ Bp0, const float* __restrict__ Bp1, const float* __restrict__ Bp2,
    const float* __restrict__ bi0, const float* __restrict__ bi1, const float* __restrict__ bi2,
    float* __restrict__ Cp0, float* __restrict__ Cp1, float* __restrict__ Cp2,
    float* __restrict__ part,
    int M, int N, int K, int splitk, int relu)
{
    extern __shared__ uint32_t smu[];

    const int z   = blockIdx.z;
    const int mat = z / splitk;
    const int kz  = z - mat * splitk;
    const float* B  = mat == 0 ? Bp0 : (mat == 1 ? Bp1 : Bp2);
    const float* bi = mat == 0 ? bi0 : (mat == 1 ? bi1 : bi2);
    float*       C  = mat == 0 ? Cp0 : (mat == 1 ? Cp1 : Cp2);

    const int tid  = threadIdx.x;
    const int lane = tid & 31;
    const int warp = tid >> 5;
    const int wm   = warp & 3;
    const int wn   = warp >> 2;
    const int gid  = lane >> 2;
    const int tkc  = lane & 3;

    const int bm = blockIdx.y * 128;
    const int bn = blockIdx.x * 128;

    const int ktot = K >> 5;
    const int ktb  = (kz * ktot) / splitk;
    const int kte  = ((kz + 1) * ktot) / splitk;
    const int nkt  = kte - ktb;

    // per-thread staging bases
    const int rowA = tid >> 3;            // 0..31
    const int segA = (tid & 7) * 4;
    const int rowB = tid >> 5;            // 0..7
    const int segB = (tid & 31) * 4;
    const float* pA = A + (long)(bm + rowA) * K + ktb * 32 + segA;
    const float* pB = B + (long)(ktb * 32 + rowB) * N + bn + segB;
    const uint32_t sbase = (uint32_t)__cvta_generic_to_shared(smu);
    const uint32_t sA = sbase + (rowA * ASTR + segA) * 4;
    const uint32_t sB = sbase + (AS_TILE + rowB * BSTR + segB) * 4;

    auto issue = [&](int i) {
        const uint32_t off = (uint32_t)((i % NSTAGE) * STAGE_U32 * 4);
        const long kf = (long)i * 32;
#pragma unroll
        for (int t = 0; t < 4; t++)
            cp16s(sA + off + t * (32 * ASTR * 4), pA + t * 32 * (long)K + kf);
#pragma unroll
        for (int t = 0; t < 4; t++)
            cp16s(sB + off + t * (8 * BSTR * 4), pB + (kf + t * 8) * (long)N);
    };

    issue(0); cp_commit();
    if (nkt > 1) { issue(1); }
    cp_commit();

    float acc[2][8][4];
#pragma unroll
    for (int mc = 0; mc < 2; mc++)
#pragma unroll
        for (int nc = 0; nc < 8; nc++)
#pragma unroll
            for (int i = 0; i < 4; i++) acc[mc][nc][i] = 0.0f;

    for (int i = 0; i < nkt; i++) {
        cp_wait<1>();
        __syncthreads();
        if (i + 2 < nkt) issue(i + 2);
        cp_commit();

        const uint32_t* as = smu + (i % NSTAGE) * STAGE_U32;
        const uint32_t* bs = as + AS_TILE;

#pragma unroll
        for (int ks = 0; ks < 4; ks++) {
            const int kc = ks * 8 + tkc;
            uint32_t af[2][4];
#pragma unroll
            for (int mc = 0; mc < 2; mc++) {
                const int r = wm * 32 + mc * 16 + gid;
                af[mc][0] = as[r * ASTR + kc];
                af[mc][1] = as[(r + 8) * ASTR + kc];
                af[mc][2] = as[r * ASTR + kc + 4];
                af[mc][3] = as[(r + 8) * ASTR + kc + 4];
            }
#pragma unroll
            for (int nc = 0; nc < 8; nc++) {
                uint32_t bf[2];
                const int c = wn * 64 + nc * 8 + gid;
                bf[0] = bs[kc * BSTR + c];
                bf[1] = bs[(kc + 4) * BSTR + c];
                mma_tf32(acc[0][nc], af[0], bf);
                mma_tf32(acc[1][nc], af[1], bf);
            }
        }
    }

    // epilogue
    if (splitk == 1) {
#pragma unroll
        for (int mc = 0; mc < 2; mc++) {
            const int r0 = bm + wm * 32 + mc * 16 + gid;
#pragma unroll
            for (int nc = 0; nc < 8; nc++) {
                const int col = bn + wn * 64 + nc * 8 + 2 * tkc;
                const float b0 = bi[col], b1 = bi[col + 1];
                float v0 = acc[mc][nc][0] + b0;
                float v1 = acc[mc][nc][1] + b1;
                float v2 = acc[mc][nc][2] + b0;
                float v3 = acc[mc][nc][3] + b1;
                if (relu) {
                    v0 = fmaxf(v0, 0.f); v1 = fmaxf(v1, 0.f);
                    v2 = fmaxf(v2, 0.f); v3 = fmaxf(v3, 0.f);
                }
                *(float2*)&C[(long)r0 * N + col]       = make_float2(v0, v1);
                *(float2*)&C[(long)(r0 + 8) * N + col] = make_float2(v2, v3);
            }
        }
    } else {
        float* P0 = part + (long)kz * M * N;
#pragma unroll
        for (int mc = 0; mc < 2; mc++) {
            const int r0 = bm + wm * 32 + mc * 16 + gid;
#pragma unroll
            for (int nc = 0; nc < 8; nc++) {
                const int col = bn + wn * 64 + nc * 8 + 2 * tkc;
                *(float2*)&P0[(long)r0 * N + col]       = make_float2(acc[mc][nc][0], acc[mc][nc][1]);
                *(float2*)&P0[(long)(r0 + 8) * N + col] = make_float2(acc[mc][nc][2], acc[mc][nc][3]);
            }
        }
    }
}

// ordered, deterministic split-K reduce + bias (+relu)
__global__ void splitk_reduce_kernel(const float* __restrict__ part,
                                     const float* __restrict__ bias,
                                     float* __restrict__ C,
                                     int MN, int N, int splitk, int relu) {
    int idx = blockIdx.x * 256 + threadIdx.x;
    if (idx >= MN) return;
    float s = part[idx];
    for (int z = 1; z < splitk; z++) s += part[(long)z * MN + idx];
    s += bias[idx % N];
    if (relu) s = fmaxf(s, 0.0f);
    C[idx] = s;
}

// ---------------- attention: one block per (b, head) ------------------------
__global__ void attn_kernel(const float* __restrict__ Q,
                            const float* __restrict__ K,
                            const float* __restrict__ V,
                            float* __restrict__ O) {
    extern __shared__ float sm[];
    float* qs = sm;
    float* ks = qs + 64 * 65;
    float* vs = ks + 64 * 65;
    float* ss = vs + 64 * 65;

    int h = blockIdx.x;
    int b = blockIdx.y;
    int tid = threadIdx.x;

    for (int e = tid; e < 4096; e += 256) {
        int s = e >> 6, d = e & 63;
        long base = ((long)(b * 64 + s) * EDIM) + h * 64 + d;
        qs[s * 65 + d] = Q[base];
        ks[s * 65 + d] = K[base];
        vs[s * 65 + d] = V[base];
    }
    __syncthreads();

    for (int e = tid; e < 4096; e += 256) {
        int row = e >> 6, col = e & 63;
        float sum = 0.0f;
#pragma unroll 16
        for (int dd = 0; dd < 64; dd++)
            sum += qs[row * 65 + dd] * ks[col * 65 + dd];
        ss[row * 65 + col] = sum * 0.125f;
    }
    __syncthreads();

    if (tid < 64) {
        float* r = ss + tid * 65;
        float m = r[0];
#pragma unroll 16
        for (int c = 1; c < 64; c++) m = fmaxf(m, r[c]);
        float sum = 0.0f;
#pragma unroll 16
        for (int c = 0; c < 64; c++) { float e = expf(r[c] - m); r[c] = e; sum += e; }
        float inv = 1.0f / sum;
#pragma unroll 16
        for (int c = 0; c < 64; c++) r[c] *= inv;
    }
    __syncthreads();

    for (int e = tid; e < 4096; e += 256) {
        int row = e >> 6, d = e & 63;
        float sum = 0.0f;
#pragma unroll 16
        for (int col = 0; col < 64; col++)
            sum += ss[row * 65 + col] * vs[col * 65 + d];
        O[(long)b * (NHEADS * SEQ * HD) + h * 4096 + row * 64 + d] = sum;
    }
}

// ------ fused: y = Σ splitk partials + gemm bias; out = LN(x + y) -----------
__global__ void add_ln_splitk_kernel(const float* __restrict__ x,
                                     const float* __restrict__ part,
                                     const float* __restrict__ gb,
                                     const float* __restrict__ g,
                                     const float* __restrict__ be,
                                     float* __restrict__ out,
                                     int MN) {
    __shared__ float buf[EDIM];
    __shared__ float red[256];
    int row = blockIdx.x;
    int tid = threadIdx.x;
    long base = (long)row * EDIM;

    float partial = 0.0f;
    for (int e = tid; e < EDIM; e += 256) {
        float y = part[base + e] + part[MN + base + e] + part[2L * MN + base + e] + gb[e];
        float v = x[base + e] + y;
        buf[e] = v;
        partial += v;
    }
    red[tid] = partial;
    __syncthreads();
    for (int s = 128; s > 0; s >>= 1) {
        if (tid < s) red[tid] += red[tid + s];
        __syncthreads();
    }
    float mean = red[0] * (1.0f / EDIM);
    __syncthreads();

    float p2 = 0.0f;
    for (int e = tid; e < EDIM; e += 256) {
        float d = buf[e] - mean;
        p2 += d * d;
    }
    red[tid] = p2;
    __syncthreads();
    for (int s = 128; s > 0; s >>= 1) {
        if (tid < s) red[tid] += red[tid + s];
        __syncthreads();
    }
    float var = red[0] * (1.0f / EDIM);
    float rstd = rsqrtf(var + 1e-6f);

    for (int e = tid; e < EDIM; e += 256)
        out[base + e] = (buf[e] - mean) * rstd * g[e] + be[e];
}

// ---------------- mean-pool + head + sigmoid --------------------------------
__global__ void head_kernel(const float* __restrict__ t,
                            const float* __restrict__ hw,
                            const float* __restrict__ hb,
                            float* __restrict__ out) {
    __shared__ float red[256];
    int b = blockIdx.x;
    int tid = threadIdx.x;
    float partial = 0.0f;
    for (int e = tid; e < EDIM; e += 256) {
        float se = 0.0f;
        for (int s = 0; s < SEQ; s++)
            se += t[((long)(b * SEQ + s)) * EDIM + e];
        partial += (se * (1.0f / SEQ)) * hw[e];
    }
    red[tid] = partial;
    __syncthreads();
    for (int s = 128; s > 0; s >>= 1) {
        if (tid < s) red[tid] += red[tid + s];
        __syncthreads();
    }
    if (tid == 0) {
        float z = red[0] + hb[0];
        out[b] = 1.0f / (1.0f + expf(-z));
    }
}

// ---------------- host launch ------------------------------------------------
static inline void launch_gemm(const float* A, const float* B, const float* bias,
                               float* C, float* part,
                               int M, int N, int K, int splitk, int relu,
                               int do_reduce) {
    dim3 grid(N / 128, M / 128, splitk);
    gemm_tf32_kernel<<<grid, 256, GEMM_SMEM>>>(A, B, B, B, bias, bias, bias,
                                               C, C, C, part, M, N, K, splitk, relu);
    if (splitk > 1 && do_reduce) {
        int MN = M * N;
        splitk_reduce_kernel<<<(MN + 255) / 256, 256>>>(part, bias, C, MN, N, splitk, relu);
    }
}

extern "C" void kernel_launch(void* const* d_in, const int* in_sizes, int n_in,
                              void* d_out, int out_size) {
    const float* x       = (const float*)d_in[0];
    const float* conv1_w = (const float*)d_in[1];
    const float* conv1_b = (const float*)d_in[2];
    const float* conv2_w = (const float*)d_in[3];
    const float* conv2_b = (const float*)d_in[4];
    const float* proj_w  = (const float*)d_in[5];
    const float* proj_b  = (const float*)d_in[6];
    const float* Wq = (const float*)d_in[7];
    const float* bq = (const float*)d_in[8];
    const float* Wk = (const float*)d_in[9];
    const float* bk = (const float*)d_in[10];
    const float* Wv = (const float*)d_in[11];
    const float* bv = (const float*)d_in[12];
    const float* Wo = (const float*)d_in[13];
    const float* bo = (const float*)d_in[14];
    const float* W1 = (const float*)d_in[15];
    const float* b1 = (const float*)d_in[16];
    const float* W2 = (const float*)d_in[17];
    const float* b2 = (const float*)d_in[18];
    const float* ln1_g = (const float*)d_in[19];
    const float* ln1_b = (const float*)d_in[20];
    const float* ln2_g = (const float*)d_in[21];
    const float* ln2_b = (const float*)d_in[22];
    const float* head_w = (const float*)d_in[23];
    const float* head_b = (const float*)d_in[24];
    float* out = (float*)d_out;

    float *pool1, *pool2, *patches, *t, *q, *k, *v, *att, *a2, *o1, *f1, *f2, *part;
    cudaGetSymbolAddress((void**)&pool1, g_pool1);
    cudaGetSymbolAddress((void**)&pool2, g_pool2);
    cudaGetSymbolAddress((void**)&patches, g_patches);
    cudaGetSymbolAddress((void**)&t,  g_t);
    cudaGetSymbolAddress((void**)&q,  g_q);
    cudaGetSymbolAddress((void**)&k,  g_k);
    cudaGetSymbolAddress((void**)&v,  g_v);
    cudaGetSymbolAddress((void**)&att, g_att);
    cudaGetSymbolAddress((void**)&a2, g_a2);
    cudaGetSymbolAddress((void**)&o1, g_o1);
    cudaGetSymbolAddress((void**)&f1, g_f1);
    cudaGetSymbolAddress((void**)&f2, g_f2);
    cudaGetSymbolAddress((void**)&part, g_part);

    const int attn_smem = 4 * 64 * 65 * sizeof(float);
    cudaFuncSetAttribute(attn_kernel, cudaFuncAttributeMaxDynamicSharedMemorySize, attn_smem);
    cudaFuncSetAttribute(gemm_tf32_kernel, cudaFuncAttributeMaxDynamicSharedMemorySize, GEMM_SMEM);

    // conv stack
    {
        int n1 = 16 * 255 * 255;
        conv1_pool_kernel<<<(n1 + 255) / 256, 256>>>(x, conv1_w, conv1_b, pool1);
        int n2 = 16 * 126 * 126;
        conv2_pool_kernel<<<(n2 + 255) / 256, 256>>>(pool1, conv2_w, conv2_b, pool2);
        long np = (long)ROWSM * PDIM;
        patch_kernel<<<(int)((np + 255) / 256), 256>>>(pool2, patches);
    }

    // patch projection (K=4096, splitk=3 -> 144 blocks)
    launch_gemm(patches, proj_w, proj_b, t, part, ROWSM, EDIM, PDIM, 3, 0, 1);

    const int MN_E = ROWSM * EDIM;

    for (int i = 0; i < NLAYER; i++) {
        const float* wq = Wq + (long)i * EDIM * EDIM;
        const float* wk = Wk + (long)i * EDIM * EDIM;
        const float* wv = Wv + (long)i * EDIM * EDIM;
        const float* wo = Wo + (long)i * EDIM * EDIM;
        const float* w1 = W1 + (long)i * EDIM * FFDIM;
        const float* w2 = W2 + (long)i * FFDIM * EDIM;

        // fused QKV: 6x8x3 = 144 blocks, one wave
        {
            dim3 grid(EDIM / 128, ROWSM / 128, 3);
            gemm_tf32_kernel<<<grid, 256, GEMM_SMEM>>>(
                t, wq, wk, wv,
                bq + i * EDIM, bk + i * EDIM, bv + i * EDIM,
                q, k, v, part, ROWSM, EDIM, EDIM, 1, 0);
        }

        attn_kernel<<<dim3(NHEADS, BB), 256, attn_smem>>>(q, k, v, att);

        // Wo (splitk=3, reduce fused into add+LN)
        launch_gemm(att, wo, bo + i * EDIM, a2, part, ROWSM, EDIM, EDIM, 3, 0, 0);
        add_ln_splitk_kernel<<<ROWSM, 256>>>(t, part, bo + i * EDIM,
                                             ln1_g + i * EDIM, ln1_b + i * EDIM, o1, MN_E);

        // FF1 (splitk=3 + relu reduce)
        launch_gemm(o1, w1, b1 + i * FFDIM, f1, part, ROWSM, FFDIM, EDIM, 3, 1, 1);

        // FF2 (splitk=3, reduce fused into add+LN)
        launch_gemm(f1, w2, b2 + i * EDIM, f2, part, ROWSM, EDIM, FFDIM, 3, 0, 0);
        add_ln_splitk_kernel<<<ROWSM, 256>>>(o1, part, b2 + i * EDIM,
                                             ln2_g + i * EDIM, ln2_b + i * EDIM, t, MN_E);
    }

    head_kernel<<<BB, 256>>>(t, head_w, head_b, out);
}